// round 1
// baseline (speedup 1.0000x reference)
#include <cuda_runtime.h>
#include <math.h>

#define BB 8
#define LDQ 512
#define LEQ 512
#define DIM 512
#define NH 8
#define DKH 64
#define FFD 2048
#define NLAY 6

// ---------------- scratch (static device globals; no allocation) ----------------
__device__ float g_x[BB * LDQ * DIM];
__device__ float g_q[BB * LDQ * DIM];
__device__ float g_k[BB * LEQ * DIM];
__device__ float g_v[BB * LEQ * DIM];
__device__ float g_ctx[BB * LDQ * DIM];
__device__ float g_proj[BB * LDQ * DIM];
__device__ float g_ffh[BB * LDQ * FFD];

// ---------------- helpers ----------------
__device__ __forceinline__ float blockReduceSum256(float v, float* red) {
    int lane = threadIdx.x & 31, wid = threadIdx.x >> 5;
#pragma unroll
    for (int o = 16; o > 0; o >>= 1) v += __shfl_xor_sync(0xffffffffu, v, o);
    if (lane == 0) red[wid] = v;
    __syncthreads();
    float r = 0.f;
    if (threadIdx.x < 8) r = red[threadIdx.x];
    if (wid == 0) {
#pragma unroll
        for (int o = 4; o > 0; o >>= 1) r += __shfl_xor_sync(0xffu, r, o);
        if (lane == 0) red[0] = r;
    }
    __syncthreads();
    float out = red[0];
    __syncthreads();
    return out;
}

__device__ __forceinline__ float blockReduceMax256(float v, float* red) {
    int lane = threadIdx.x & 31, wid = threadIdx.x >> 5;
#pragma unroll
    for (int o = 16; o > 0; o >>= 1) v = fmaxf(v, __shfl_xor_sync(0xffffffffu, v, o));
    if (lane == 0) red[wid] = v;
    __syncthreads();
    float r = -1e30f;
    if (threadIdx.x < 8) r = red[threadIdx.x];
    if (wid == 0) {
#pragma unroll
        for (int o = 4; o > 0; o >>= 1) r = fmaxf(r, __shfl_xor_sync(0xffu, r, o));
        if (lane == 0) red[0] = r;
    }
    __syncthreads();
    float out = red[0];
    __syncthreads();
    return out;
}

// ---------------- embedding + sinusoidal position ----------------
__global__ __launch_bounds__(256) void embed_kernel(const int* __restrict__ dec,
                                                    const float* __restrict__ emb,
                                                    float* __restrict__ x) {
    int idx = blockIdx.x * 256 + threadIdx.x;
    if (idx >= BB * LDQ * DIM) return;
    int d = idx & (DIM - 1);
    int bl = idx / DIM;
    int l = bl & (LDQ - 1);
    int tok = dec[bl];
    double pos = (double)(l + 1);
    int jhalf = d >> 1;
    double denom = pow(10000.0, (double)(2 * jhalf) / (double)DIM);
    double a = pos / denom;
    float pe = ((d & 1) == 0) ? (float)sin(a) : (float)cos(a);
    x[idx] = emb[(size_t)tok * DIM + d] + pe;
}

// ---------------- generic GEMM: C[M,N] = A[M,K] * W[N,K]^T + bias[N] ----------------
__global__ __launch_bounds__(256) void gemm_bias(const float* __restrict__ A,
                                                 const float* __restrict__ W,
                                                 const float* __restrict__ bias,
                                                 float* __restrict__ C,
                                                 int M, int N, int K, int relu) {
    __shared__ float As[64][17];
    __shared__ float Ws[64][17];
    int tid = threadIdx.x;
    int tx = tid & 15, ty = tid >> 4;
    int m0 = blockIdx.y * 64, n0 = blockIdx.x * 64;
    float acc[4][4] = {};
    for (int k0 = 0; k0 < K; k0 += 16) {
#pragma unroll
        for (int i = tid; i < 1024; i += 256) {
            int r = i >> 4, kk = i & 15;
            As[r][kk] = A[(size_t)(m0 + r) * K + k0 + kk];
            Ws[r][kk] = W[(size_t)(n0 + r) * K + k0 + kk];
        }
        __syncthreads();
#pragma unroll
        for (int kk = 0; kk < 16; kk++) {
            float a[4], bv[4];
#pragma unroll
            for (int i = 0; i < 4; i++) a[i] = As[ty * 4 + i][kk];
#pragma unroll
            for (int j = 0; j < 4; j++) bv[j] = Ws[tx * 4 + j][kk];
#pragma unroll
            for (int i = 0; i < 4; i++)
#pragma unroll
                for (int j = 0; j < 4; j++) acc[i][j] = fmaf(a[i], bv[j], acc[i][j]);
        }
        __syncthreads();
    }
#pragma unroll
    for (int i = 0; i < 4; i++) {
        int m = m0 + ty * 4 + i;
#pragma unroll
        for (int j = 0; j < 4; j++) {
            int n = n0 + tx * 4 + j;
            float v = acc[i][j] + bias[n];
            if (relu) v = fmaxf(v, 0.f);
            C[(size_t)m * N + n] = v;
        }
    }
}

// ---------------- attention scores: S[bh,q,k] = scale*Q.K^T with mask ----------------
__global__ __launch_bounds__(256) void attn_scores(const float* __restrict__ Q,
                                                   const float* __restrict__ Kb_,
                                                   const int* __restrict__ tok,
                                                   int causal,
                                                   float* __restrict__ S, int Lk) {
    int bh = blockIdx.z;
    int b = bh / NH, h = bh % NH;
    const float* Qb = Q + (size_t)b * LDQ * DIM + h * DKH;
    const float* Kb = Kb_ + (size_t)b * Lk * DIM + h * DKH;
    __shared__ float Qs[64][65];
    __shared__ float Ks[64][65];
    int tid = threadIdx.x;
    int q0 = blockIdx.y * 64, k0 = blockIdx.x * 64;
#pragma unroll
    for (int i = tid; i < 4096; i += 256) {
        int r = i >> 6, c = i & 63;
        Qs[r][c] = Qb[(size_t)(q0 + r) * DIM + c];
        Ks[r][c] = Kb[(size_t)(k0 + r) * DIM + c];
    }
    __syncthreads();
    int tx = tid & 15, ty = tid >> 4;
    float acc[4][4] = {};
#pragma unroll
    for (int d = 0; d < 64; d++) {
        float a[4], bv[4];
#pragma unroll
        for (int i = 0; i < 4; i++) a[i] = Qs[ty * 4 + i][d];
#pragma unroll
        for (int j = 0; j < 4; j++) bv[j] = Ks[tx * 4 + j][d];
#pragma unroll
        for (int i = 0; i < 4; i++)
#pragma unroll
            for (int j = 0; j < 4; j++) acc[i][j] = fmaf(a[i], bv[j], acc[i][j]);
    }
    float* Srow = S + (size_t)bh * LDQ * Lk;
#pragma unroll
    for (int i = 0; i < 4; i++) {
        int q = q0 + ty * 4 + i;
#pragma unroll
        for (int j = 0; j < 4; j++) {
            int k = k0 + tx * 4 + j;
            float v = acc[i][j] * 0.125f;
            bool msk = (tok[b * Lk + k] == 0) || (causal && (k > q));
            Srow[(size_t)q * Lk + k] = msk ? -1e9f : v;
        }
    }
}

// ---------------- row softmax over 512 (in place) ----------------
__global__ __launch_bounds__(256) void softmax_rows(float* __restrict__ S) {
    float* row = S + (size_t)blockIdx.x * 512;
    int t = threadIdx.x;
    __shared__ float red[32];
    float v0 = row[t], v1 = row[t + 256];
    float m = blockReduceMax256(fmaxf(v0, v1), red);
    float e0 = expf(v0 - m), e1 = expf(v1 - m);
    float s = blockReduceSum256(e0 + e1, red);
    float inv = 1.f / s;
    row[t] = e0 * inv;
    row[t + 256] = e1 * inv;
}

// ---------------- ctx: C[b,q,h*64+d] = sum_k W[bh,q,k] * V[b,k,h*64+d] ----------------
__global__ __launch_bounds__(256) void attn_ctx(const float* __restrict__ S,
                                                const float* __restrict__ Vb_,
                                                float* __restrict__ C, int Lk) {
    int bh = blockIdx.y;
    int b = bh / NH, h = bh % NH;
    const float* Sb = S + (size_t)bh * LDQ * Lk;
    const float* Vp = Vb_ + (size_t)b * Lk * DIM + h * DKH;
    float* Cp = C + (size_t)b * LDQ * DIM + h * DKH;
    int q0 = blockIdx.x * 64;
    __shared__ float Wt[64][65];
    __shared__ float Vt[64][65];
    int tid = threadIdx.x, tx = tid & 15, ty = tid >> 4;
    float acc[4][4] = {};
    for (int k0 = 0; k0 < Lk; k0 += 64) {
#pragma unroll
        for (int i = tid; i < 4096; i += 256) {
            int r = i >> 6, c = i & 63;
            Wt[r][c] = Sb[(size_t)(q0 + r) * Lk + k0 + c];
            Vt[r][c] = Vp[(size_t)(k0 + r) * DIM + c];
        }
        __syncthreads();
#pragma unroll
        for (int kk = 0; kk < 64; kk++) {
            float a[4], bv[4];
#pragma unroll
            for (int i = 0; i < 4; i++) a[i] = Wt[ty * 4 + i][kk];
#pragma unroll
            for (int j = 0; j < 4; j++) bv[j] = Vt[kk][tx * 4 + j];
#pragma unroll
            for (int i = 0; i < 4; i++)
#pragma unroll
                for (int j = 0; j < 4; j++) acc[i][j] = fmaf(a[i], bv[j], acc[i][j]);
        }
        __syncthreads();
    }
#pragma unroll
    for (int i = 0; i < 4; i++)
#pragma unroll
        for (int j = 0; j < 4; j++)
            Cp[(size_t)(q0 + ty * 4 + i) * DIM + tx * 4 + j] = acc[i][j];
}

// ---------------- residual add + layernorm ----------------
__global__ __launch_bounds__(256) void add_ln(const float* __restrict__ A,
                                              const float* __restrict__ R,
                                              const float* __restrict__ g,
                                              const float* __restrict__ be,
                                              float* __restrict__ out) {
    int row = blockIdx.x;
    int t = threadIdx.x;
    __shared__ float red[32];
    const float* a = A + (size_t)row * DIM;
    const float* r = R + (size_t)row * DIM;
    float x0 = a[t] + r[t];
    float x1 = a[t + 256] + r[t + 256];
    float s = blockReduceSum256(x0 + x1, red);
    float mean = s * (1.f / 512.f);
    float d0 = x0 - mean, d1 = x1 - mean;
    float s2 = blockReduceSum256(d0 * d0 + d1 * d1, red);
    float inv = rsqrtf(s2 * (1.f / 512.f) + 1e-5f);
    out[(size_t)row * DIM + t] = d0 * inv * g[t] + be[t];
    out[(size_t)row * DIM + t + 256] = d1 * inv * g[t + 256] + be[t + 256];
}

// ---------------- host orchestration ----------------
extern "C" void kernel_launch(void* const* d_in, const int* in_sizes, int n_in,
                              void* d_out, int out_size) {
    const int* dec = (const int*)d_in[0];
    const int* enc = (const int*)d_in[1];
    const float* enc_out = (const float*)d_in[2];
    const float* emb = (const float*)d_in[3];

    // Disambiguate metadata ordering: dict order (wq,wk,wv,wo,bq,...) vs
    // signature order (wq,bq,wk,bk,...). in_sizes[5] is NL*D*D for dict order,
    // NL*D for signature order. Deterministic.
    bool dict_order = (in_sizes[5] == NLAY * DIM * DIM);
    int iwq[2], iwk[2], iwv[2], iwo[2], ibq[2], ibk[2], ibv[2], ibo[2], ig[2], ib[2];
    for (int p = 0; p < 2; p++) {
        int base = 4 + p * 10;
        if (dict_order) {
            iwq[p] = base + 0; iwk[p] = base + 1; iwv[p] = base + 2; iwo[p] = base + 3;
            ibq[p] = base + 4; ibk[p] = base + 5; ibv[p] = base + 6; ibo[p] = base + 7;
            ig[p] = base + 8; ib[p] = base + 9;
        } else {
            iwq[p] = base + 0; ibq[p] = base + 1; iwk[p] = base + 2; ibk[p] = base + 3;
            iwv[p] = base + 4; ibv[p] = base + 5; iwo[p] = base + 6; ibo[p] = base + 7;
            ig[p] = base + 8; ib[p] = base + 9;
        }
    }
    const float* ffn_w1 = (const float*)d_in[24];
    const float* ffn_b1 = (const float*)d_in[25];
    const float* ffn_w2 = (const float*)d_in[26];
    const float* ffn_b2 = (const float*)d_in[27];
    const float* ffn_g = (const float*)d_in[28];
    const float* ffn_bb = (const float*)d_in[29];

    float *x, *q, *k, *v, *ctxp, *proj, *ffh;
    cudaGetSymbolAddress((void**)&x, g_x);
    cudaGetSymbolAddress((void**)&q, g_q);
    cudaGetSymbolAddress((void**)&k, g_k);
    cudaGetSymbolAddress((void**)&v, g_v);
    cudaGetSymbolAddress((void**)&ctxp, g_ctx);
    cudaGetSymbolAddress((void**)&proj, g_proj);
    cudaGetSymbolAddress((void**)&ffh, g_ffh);

    float* out = (float*)d_out;
    const size_t XSZ = (size_t)BB * LDQ * DIM;
    const size_t AW = (size_t)BB * NH * LDQ * LDQ;  // per-layer attn weight size
    float* sa_base = out + XSZ;
    float* ca_base = out + XSZ + (size_t)NLAY * AW;

    const int M = BB * LDQ;  // 4096 rows (also B*LE for enc projections)

    embed_kernel<<<(BB * LDQ * DIM + 255) / 256, 256>>>(dec, emb, x);

    for (int l = 0; l < NLAY; l++) {
        size_t wofs = (size_t)l * DIM * DIM;
        size_t bofs = (size_t)l * DIM;

        for (int p = 0; p < 2; p++) {
            const float* wq = (const float*)d_in[iwq[p]] + wofs;
            const float* wk = (const float*)d_in[iwk[p]] + wofs;
            const float* wv = (const float*)d_in[iwv[p]] + wofs;
            const float* wo = (const float*)d_in[iwo[p]] + wofs;
            const float* bq = (const float*)d_in[ibq[p]] + bofs;
            const float* bk = (const float*)d_in[ibk[p]] + bofs;
            const float* bv = (const float*)d_in[ibv[p]] + bofs;
            const float* bo = (const float*)d_in[ibo[p]] + bofs;
            const float* gg = (const float*)d_in[ig[p]] + bofs;
            const float* bt = (const float*)d_in[ib[p]] + bofs;

            const float* kv_src = (p == 0) ? x : enc_out;
            const int* tok = (p == 0) ? dec : enc;
            int causal = (p == 0) ? 1 : 0;
            float* S = ((p == 0) ? sa_base : ca_base) + (size_t)l * AW;

            gemm_bias<<<dim3(8, 64), 256>>>(x, wq, bq, q, M, DIM, DIM, 0);
            gemm_bias<<<dim3(8, 64), 256>>>(kv_src, wk, bk, k, M, DIM, DIM, 0);
            gemm_bias<<<dim3(8, 64), 256>>>(kv_src, wv, bv, v, M, DIM, DIM, 0);
            attn_scores<<<dim3(8, 8, BB * NH), 256>>>(q, k, tok, causal, S, 512);
            softmax_rows<<<BB * NH * LDQ, 256>>>(S);
            attn_ctx<<<dim3(8, BB * NH), 256>>>(S, v, ctxp, 512);
            gemm_bias<<<dim3(8, 64), 256>>>(ctxp, wo, bo, proj, M, DIM, DIM, 0);
            add_ln<<<M, 256>>>(proj, x, gg, bt, x);
        }

        // FFN
        gemm_bias<<<dim3(32, 64), 256>>>(x, ffn_w1 + (size_t)l * FFD * DIM,
                                         ffn_b1 + (size_t)l * FFD, ffh, M, FFD, DIM, 1);
        gemm_bias<<<dim3(8, 64), 256>>>(ffh, ffn_w2 + (size_t)l * DIM * FFD,
                                        ffn_b2 + bofs, proj, M, DIM, FFD, 0);
        float* lnout = (l == NLAY - 1) ? out : x;
        add_ln<<<M, 256>>>(proj, x, ffn_g + bofs, ffn_bb + bofs, lnout);
    }
}

// round 3
// speedup vs baseline: 2.9091x; 2.9091x over previous
#include <cuda_runtime.h>
#include <cstdint>
#include <math.h>

#define BB 8
#define LDQ 512
#define DIM 512
#define NH 8
#define FFD 2048
#define NLAY 6

// ---------------- scratch (static device globals; no allocation) ----------------
__device__ float g_x[BB * LDQ * DIM];
__device__ float g_q[BB * LDQ * DIM];
__device__ float g_k[BB * LDQ * DIM];
__device__ float g_vt[DIM * BB * LDQ];   // transposed V: [d_global][token]
__device__ float g_ctx[BB * LDQ * DIM];
__device__ float g_proj[BB * LDQ * DIM];
__device__ float g_ffh[BB * LDQ * FFD];

// ---------------- small helpers ----------------
__device__ __forceinline__ float tf32r(float x) {
    uint32_t u;
    asm("cvt.rna.tf32.f32 %0, %1;" : "=r"(u) : "f"(x));
    return __uint_as_float(u);
}

__device__ __forceinline__ void mma_tf32(float* c, const uint32_t* a, const uint32_t* b) {
    asm volatile(
        "mma.sync.aligned.m16n8k8.row.col.f32.tf32.tf32.f32 "
        "{%0,%1,%2,%3}, {%4,%5,%6,%7}, {%8,%9}, {%0,%1,%2,%3};"
        : "+f"(c[0]), "+f"(c[1]), "+f"(c[2]), "+f"(c[3])
        : "r"(a[0]), "r"(a[1]), "r"(a[2]), "r"(a[3]), "r"(b[0]), "r"(b[1]));
}

struct GP {
    const float* A; long long lda, aB, aH;
    const float* B; long long ldb, bB, bH;
    float* C;       long long ldc, cB, cH;
    const float* bias;
    const int* tok;
    int K, relu, causal;
};

// MODE 0: C = A*B^T (+bias)(+relu)
// MODE 1: scores:  C = mask(A*B^T * 0.125)
// MODE 2: C^T store: C[n][m] = A*B^T (+bias)
// Block tile: 128(M) x BN(N), K-chunk 32, 256 threads (8 warps, 4x2), tf32 mma.sync.
template <int MODE, int BN>
__global__ __launch_bounds__(256) void gemm_mma(GP p) {
    extern __shared__ float sm[];
    constexpr int ST = 36;               // smem row stride (floats); conflict-free frags
    constexpr int ATILE = 128 * ST;
    constexpr int BTILE = BN * ST;
    constexpr int NT = BN / 16;          // n8 tiles per warp (2 warps along N)
    constexpr int BLD = BN / 32;         // float4 B loads per thread

    float* As0 = sm;
    float* As1 = sm + ATILE;
    float* Bs0 = sm + 2 * ATILE;
    float* Bs1 = sm + 2 * ATILE + BTILE;

    int tid = threadIdx.x, lane = tid & 31, wid = tid >> 5;
    int warp_m = wid & 3, warp_n = wid >> 2;
    int b = blockIdx.z / NH, h = blockIdx.z % NH;

    const float* Ab = p.A + (size_t)b * p.aB + (size_t)h * p.aH +
                      (size_t)(blockIdx.y * 128) * p.lda;
    const float* Bb = p.B + (size_t)b * p.bB + (size_t)h * p.bH +
                      (size_t)(blockIdx.x * BN) * p.ldb;

    float acc[2][NT][4];
#pragma unroll
    for (int mt = 0; mt < 2; mt++)
#pragma unroll
        for (int nt = 0; nt < NT; nt++)
#pragma unroll
            for (int i = 0; i < 4; i++) acc[mt][nt][i] = 0.f;

    const int nc = p.K >> 5;
    float4 rA[4], rB[BLD];

    auto fetch = [&](int c) {
        int k0 = c << 5;
#pragma unroll
        for (int j = 0; j < 4; j++) {
            int i = tid + j * 256;
            int r = i >> 3, c4 = i & 7;
            rA[j] = *(const float4*)(Ab + (size_t)r * p.lda + k0 + c4 * 4);
        }
#pragma unroll
        for (int j = 0; j < BLD; j++) {
            int i = tid + j * 256;
            int r = i >> 3, c4 = i & 7;
            rB[j] = *(const float4*)(Bb + (size_t)r * p.ldb + k0 + c4 * 4);
        }
    };
    auto stash = [&](float* Ad, float* Bd) {
#pragma unroll
        for (int j = 0; j < 4; j++) {
            int i = tid + j * 256;
            int r = i >> 3, c4 = i & 7;
            float* d = Ad + r * ST + c4 * 4;
            d[0] = tf32r(rA[j].x); d[1] = tf32r(rA[j].y);
            d[2] = tf32r(rA[j].z); d[3] = tf32r(rA[j].w);
        }
#pragma unroll
        for (int j = 0; j < BLD; j++) {
            int i = tid + j * 256;
            int r = i >> 3, c4 = i & 7;
            float* d = Bd + r * ST + c4 * 4;
            d[0] = tf32r(rB[j].x); d[1] = tf32r(rB[j].y);
            d[2] = tf32r(rB[j].z); d[3] = tf32r(rB[j].w);
        }
    };

    fetch(0);
    stash(As0, Bs0);
    __syncthreads();

    for (int c = 0; c < nc; c++) {
        float* Ac = (c & 1) ? As1 : As0;
        float* Bc = (c & 1) ? Bs1 : Bs0;
        if (c + 1 < nc) fetch(c + 1);

#pragma unroll
        for (int ks = 0; ks < 4; ks++) {
            int kb = ks * 8 + (lane & 3);
            uint32_t af[2][4];
            int ar = warp_m * 32 + (lane >> 2);
#pragma unroll
            for (int mt = 0; mt < 2; mt++) {
                const float* ap = Ac + (ar + mt * 16) * ST + kb;
                af[mt][0] = __float_as_uint(ap[0]);
                af[mt][1] = __float_as_uint(ap[8 * ST]);
                af[mt][2] = __float_as_uint(ap[4]);
                af[mt][3] = __float_as_uint(ap[8 * ST + 4]);
            }
            uint32_t bf[NT][2];
            int br = warp_n * (NT * 8) + (lane >> 2);
#pragma unroll
            for (int nt = 0; nt < NT; nt++) {
                const float* bp = Bc + (br + nt * 8) * ST + kb;
                bf[nt][0] = __float_as_uint(bp[0]);
                bf[nt][1] = __float_as_uint(bp[4]);
            }
#pragma unroll
            for (int mt = 0; mt < 2; mt++)
#pragma unroll
                for (int nt = 0; nt < NT; nt++)
                    mma_tf32(acc[mt][nt], af[mt], bf[nt]);
        }

        if (c + 1 < nc) stash((c & 1) ? As0 : As1, (c & 1) ? Bs0 : Bs1);
        __syncthreads();
    }

    // ---------------- epilogue ----------------
    float* Cb = p.C + (size_t)b * p.cB + (size_t)h * p.cH;
    const int* tokb = p.tok ? (p.tok + b * 512) : nullptr;
    int mbase = blockIdx.y * 128 + warp_m * 32 + (lane >> 2);
    int nbase = blockIdx.x * BN + warp_n * (NT * 8) + (lane & 3) * 2;

#pragma unroll
    for (int mt = 0; mt < 2; mt++) {
#pragma unroll
        for (int nt = 0; nt < NT; nt++) {
            int n = nbase + nt * 8;
#pragma unroll
            for (int hf = 0; hf < 2; hf++) {
                int m = mbase + mt * 16 + hf * 8;
                float v0 = acc[mt][nt][hf * 2];
                float v1 = acc[mt][nt][hf * 2 + 1];
                if (MODE == 0) {
                    if (p.bias) { v0 += p.bias[n]; v1 += p.bias[n + 1]; }
                    if (p.relu) { v0 = fmaxf(v0, 0.f); v1 = fmaxf(v1, 0.f); }
                    float2 o = {v0, v1};
                    *(float2*)(Cb + (size_t)m * p.ldc + n) = o;
                } else if (MODE == 1) {
                    v0 *= 0.125f; v1 *= 0.125f;
                    if (tokb[n] == 0 || (p.causal && n > m)) v0 = -1e9f;
                    if (tokb[n + 1] == 0 || (p.causal && n + 1 > m)) v1 = -1e9f;
                    float2 o = {v0, v1};
                    *(float2*)(Cb + (size_t)m * p.ldc + n) = o;
                } else {
                    if (p.bias) { v0 += p.bias[n]; v1 += p.bias[n + 1]; }
                    Cb[(size_t)n * p.ldc + m] = v0;
                    Cb[(size_t)(n + 1) * p.ldc + m] = v1;
                }
            }
        }
    }
}

// ---------------- reductions ----------------
__device__ __forceinline__ float blockReduceSum256(float v, float* red) {
    int lane = threadIdx.x & 31, wid = threadIdx.x >> 5;
#pragma unroll
    for (int o = 16; o > 0; o >>= 1) v += __shfl_xor_sync(0xffffffffu, v, o);
    if (lane == 0) red[wid] = v;
    __syncthreads();
    float r = 0.f;
    if (threadIdx.x < 8) r = red[threadIdx.x];
    if (wid == 0) {
#pragma unroll
        for (int o = 4; o > 0; o >>= 1) r += __shfl_xor_sync(0xffu, r, o);
        if (lane == 0) red[0] = r;
    }
    __syncthreads();
    float out = red[0];
    __syncthreads();
    return out;
}

__device__ __forceinline__ float blockReduceMax256(float v, float* red) {
    int lane = threadIdx.x & 31, wid = threadIdx.x >> 5;
#pragma unroll
    for (int o = 16; o > 0; o >>= 1) v = fmaxf(v, __shfl_xor_sync(0xffffffffu, v, o));
    if (lane == 0) red[wid] = v;
    __syncthreads();
    float r = -1e30f;
    if (threadIdx.x < 8) r = red[threadIdx.x];
    if (wid == 0) {
#pragma unroll
        for (int o = 4; o > 0; o >>= 1) r = fmaxf(r, __shfl_xor_sync(0xffu, r, o));
        if (lane == 0) red[0] = r;
    }
    __syncthreads();
    float out = red[0];
    __syncthreads();
    return out;
}

// ---------------- embedding + sinusoidal position ----------------
__global__ __launch_bounds__(256) void embed_kernel(const int* __restrict__ dec,
                                                    const float* __restrict__ emb,
                                                    float* __restrict__ x) {
    int idx = blockIdx.x * 256 + threadIdx.x;
    if (idx >= BB * LDQ * DIM) return;
    int d = idx & (DIM - 1);
    int bl = idx / DIM;
    int l = bl & (LDQ - 1);
    int tok = dec[bl];
    double pos = (double)(l + 1);
    int jhalf = d >> 1;
    double denom = pow(10000.0, (double)(2 * jhalf) / (double)DIM);
    double a = pos / denom;
    float pe = ((d & 1) == 0) ? (float)sin(a) : (float)cos(a);
    x[idx] = emb[(size_t)tok * DIM + d] + pe;
}

// ---------------- row softmax over 512 (in place) ----------------
__global__ __launch_bounds__(256) void softmax_rows(float* __restrict__ S) {
    float* row = S + (size_t)blockIdx.x * 512;
    int t = threadIdx.x;
    __shared__ float red[32];
    float v0 = row[t], v1 = row[t + 256];
    float m = blockReduceMax256(fmaxf(v0, v1), red);
    float e0 = expf(v0 - m), e1 = expf(v1 - m);
    float s = blockReduceSum256(e0 + e1, red);
    float inv = 1.f / s;
    row[t] = e0 * inv;
    row[t + 256] = e1 * inv;
}

// ---------------- residual add + layernorm ----------------
__global__ __launch_bounds__(256) void add_ln(const float* __restrict__ A,
                                              const float* __restrict__ R,
                                              const float* __restrict__ g,
                                              const float* __restrict__ be,
                                              float* __restrict__ out) {
    int row = blockIdx.x;
    int t = threadIdx.x;
    __shared__ float red[32];
    const float* a = A + (size_t)row * DIM;
    const float* r = R + (size_t)row * DIM;
    float x0 = a[t] + r[t];
    float x1 = a[t + 256] + r[t + 256];
    float s = blockReduceSum256(x0 + x1, red);
    float mean = s * (1.f / 512.f);
    float d0 = x0 - mean, d1 = x1 - mean;
    float s2 = blockReduceSum256(d0 * d0 + d1 * d1, red);
    float inv = rsqrtf(s2 * (1.f / 512.f) + 1e-5f);
    out[(size_t)row * DIM + t] = d0 * inv * g[t] + be[t];
    out[(size_t)row * DIM + t + 256] = d1 * inv * g[t + 256] + be[t + 256];
}

// ---------------- host orchestration ----------------
#define SMEM128 (2 * (128 + 128) * 36 * 4)
#define SMEM64  (2 * (128 + 64) * 36 * 4)

extern "C" void kernel_launch(void* const* d_in, const int* in_sizes, int n_in,
                              void* d_out, int out_size) {
    const int* dec = (const int*)d_in[0];
    const int* enc = (const int*)d_in[1];
    const float* enc_out = (const float*)d_in[2];
    const float* emb = (const float*)d_in[3];

    bool dict_order = (in_sizes[5] == NLAY * DIM * DIM);
    int iwq[2], iwk[2], iwv[2], iwo[2], ibq[2], ibk[2], ibv[2], ibo[2], ig[2], ib[2];
    for (int p = 0; p < 2; p++) {
        int base = 4 + p * 10;
        if (dict_order) {
            iwq[p] = base + 0; iwk[p] = base + 1; iwv[p] = base + 2; iwo[p] = base + 3;
            ibq[p] = base + 4; ibk[p] = base + 5; ibv[p] = base + 6; ibo[p] = base + 7;
            ig[p] = base + 8; ib[p] = base + 9;
        } else {
            iwq[p] = base + 0; ibq[p] = base + 1; iwk[p] = base + 2; ibk[p] = base + 3;
            iwv[p] = base + 4; ibv[p] = base + 5; iwo[p] = base + 6; ibo[p] = base + 7;
            ig[p] = base + 8; ib[p] = base + 9;
        }
    }
    const float* ffn_w1 = (const float*)d_in[24];
    const float* ffn_b1 = (const float*)d_in[25];
    const float* ffn_w2 = (const float*)d_in[26];
    const float* ffn_b2 = (const float*)d_in[27];
    const float* ffn_g = (const float*)d_in[28];
    const float* ffn_bb = (const float*)d_in[29];

    float *x, *q, *k, *vt, *ctxp, *proj, *ffh;
    cudaGetSymbolAddress((void**)&x, g_x);
    cudaGetSymbolAddress((void**)&q, g_q);
    cudaGetSymbolAddress((void**)&k, g_k);
    cudaGetSymbolAddress((void**)&vt, g_vt);
    cudaGetSymbolAddress((void**)&ctxp, g_ctx);
    cudaGetSymbolAddress((void**)&proj, g_proj);
    cudaGetSymbolAddress((void**)&ffh, g_ffh);

    cudaFuncSetAttribute(gemm_mma<0, 128>, cudaFuncAttributeMaxDynamicSharedMemorySize, SMEM128);
    cudaFuncSetAttribute(gemm_mma<1, 128>, cudaFuncAttributeMaxDynamicSharedMemorySize, SMEM128);
    cudaFuncSetAttribute(gemm_mma<2, 128>, cudaFuncAttributeMaxDynamicSharedMemorySize, SMEM128);
    cudaFuncSetAttribute(gemm_mma<0, 64>, cudaFuncAttributeMaxDynamicSharedMemorySize, SMEM64);

    float* out = (float*)d_out;
    const size_t XSZ = (size_t)BB * LDQ * DIM;
    const size_t AW = (size_t)BB * NH * LDQ * LDQ;
    float* sa_base = out + XSZ;
    float* ca_base = out + XSZ + (size_t)NLAY * AW;

    const int M = BB * LDQ;                     // 4096
    const long long LL = (long long)LDQ * LDQ;  // per-(b,h) score block

    embed_kernel<<<(BB * LDQ * DIM + 255) / 256, 256>>>(dec, emb, x);

    for (int l = 0; l < NLAY; l++) {
        size_t wofs = (size_t)l * DIM * DIM;
        size_t bofs = (size_t)l * DIM;

        for (int p = 0; p < 2; p++) {
            const float* wq = (const float*)d_in[iwq[p]] + wofs;
            const float* wk = (const float*)d_in[iwk[p]] + wofs;
            const float* wv = (const float*)d_in[iwv[p]] + wofs;
            const float* wo = (const float*)d_in[iwo[p]] + wofs;
            const float* bq = (const float*)d_in[ibq[p]] + bofs;
            const float* bk = (const float*)d_in[ibk[p]] + bofs;
            const float* bv = (const float*)d_in[ibv[p]] + bofs;
            const float* bo = (const float*)d_in[ibo[p]] + bofs;
            const float* gg = (const float*)d_in[ig[p]] + bofs;
            const float* bt = (const float*)d_in[ib[p]] + bofs;

            const float* kv_src = (p == 0) ? x : enc_out;
            const int* tok = (p == 0) ? dec : enc;
            int causal = (p == 0) ? 1 : 0;
            float* S = ((p == 0) ? sa_base : ca_base) + (size_t)l * AW;

            GP gp;
            // Q = x * wq^T + bq
            gp = GP{x, DIM, 0, 0, wq, DIM, 0, 0, q, DIM, 0, 0, bq, nullptr, DIM, 0, 0};
            gemm_mma<0, 128><<<dim3(4, 32, 1), 256, SMEM128>>>(gp);
            // K = kv * wk^T + bk
            gp = GP{kv_src, DIM, 0, 0, wk, DIM, 0, 0, k, DIM, 0, 0, bk, nullptr, DIM, 0, 0};
            gemm_mma<0, 128><<<dim3(4, 32, 1), 256, SMEM128>>>(gp);
            // V^T = (kv * wv^T + bv)^T  -> vt[d][token]
            gp = GP{kv_src, DIM, 0, 0, wv, DIM, 0, 0, vt, M, 0, 0, bv, nullptr, DIM, 0, 0};
            gemm_mma<2, 128><<<dim3(4, 32, 1), 256, SMEM128>>>(gp);
            // scores
            gp = GP{q, DIM, LL, 64, k, DIM, LL, 64, S, LDQ, NH * LL, LL,
                    nullptr, tok, 64, 0, causal};
            gemm_mma<1, 128><<<dim3(4, 4, BB * NH), 256, SMEM128>>>(gp);
            softmax_rows<<<BB * NH * LDQ, 256>>>(S);
            // ctx[b,q,h*64+d] = sum_k S[b,h,q,k] * vt[h*64+d][b*512+k]
            gp = GP{S, LDQ, NH * LL, LL, vt, M, LDQ, 64LL * M, ctxp, DIM, LL, 64,
                    nullptr, nullptr, 512, 0, 0};
            gemm_mma<0, 64><<<dim3(1, 4, BB * NH), 256, SMEM64>>>(gp);
            // out proj
            gp = GP{ctxp, DIM, 0, 0, wo, DIM, 0, 0, proj, DIM, 0, 0, bo, nullptr, DIM, 0, 0};
            gemm_mma<0, 128><<<dim3(4, 32, 1), 256, SMEM128>>>(gp);
            add_ln<<<M, 256>>>(proj, x, gg, bt, x);
        }

        // FFN
        GP gp;
        gp = GP{x, DIM, 0, 0, ffn_w1 + (size_t)l * FFD * DIM, DIM, 0, 0,
                ffh, FFD, 0, 0, ffn_b1 + (size_t)l * FFD, nullptr, DIM, 1, 0};
        gemm_mma<0, 128><<<dim3(16, 32, 1), 256, SMEM128>>>(gp);
        gp = GP{ffh, FFD, 0, 0, ffn_w2 + (size_t)l * DIM * FFD, FFD, 0, 0,
                proj, DIM, 0, 0, ffn_b2 + bofs, nullptr, FFD, 0, 0};
        gemm_mma<0, 128><<<dim3(4, 32, 1), 256, SMEM128>>>(gp);
        float* lnout = (l == NLAY - 1) ? out : x;
        add_ln<<<M, 256>>>(proj, x, ffn_g + bofs, ffn_bb + bofs, lnout);
    }
}

// round 4
// speedup vs baseline: 3.0565x; 1.0506x over previous
#include <cuda_runtime.h>
#include <cstdint>
#include <math.h>

#define BB 8
#define LDQ 512
#define DIM 512
#define NH 8
#define FFD 2048
#define NLAY 6

// ---------------- scratch (static device globals; no allocation) ----------------
__device__ float g_x[BB * LDQ * DIM];
__device__ float g_q[BB * LDQ * DIM];
__device__ float g_k[BB * LDQ * DIM];
__device__ float g_vt[DIM * BB * LDQ];   // transposed V: [d_global][token]
__device__ float g_ctx[BB * LDQ * DIM];
__device__ float g_proj[BB * LDQ * DIM];
__device__ float g_ffh[BB * LDQ * FFD];

// ---------------- small helpers ----------------
__device__ __forceinline__ float tf32r(float x) {
    uint32_t u;
    asm("cvt.rna.tf32.f32 %0, %1;" : "=r"(u) : "f"(x));
    return __uint_as_float(u);
}

__device__ __forceinline__ void mma_tf32(float* c, const uint32_t* a, const uint32_t* b) {
    asm volatile(
        "mma.sync.aligned.m16n8k8.row.col.f32.tf32.tf32.f32 "
        "{%0,%1,%2,%3}, {%4,%5,%6,%7}, {%8,%9}, {%0,%1,%2,%3};"
        : "+f"(c[0]), "+f"(c[1]), "+f"(c[2]), "+f"(c[3])
        : "r"(a[0]), "r"(a[1]), "r"(a[2]), "r"(a[3]), "r"(b[0]), "r"(b[1]));
}

// ---------------- core: 128 x BN tile, K-chunk 32, double-buffered ----------------
template <int BN>
__device__ __forceinline__ void gemm_core(const float* __restrict__ Ab, long long lda,
                                          const float* __restrict__ Bb, long long ldb,
                                          int K, float* sm, int tid, int lane,
                                          int warp_m, int warp_n,
                                          float (&acc)[2][BN / 16][4]) {
    constexpr int ST = 36;
    constexpr int ATILE = 128 * ST;
    constexpr int BTILE = BN * ST;
    constexpr int NT = BN / 16;
    constexpr int BLD = BN / 32;

    float* As0 = sm;
    float* As1 = sm + ATILE;
    float* Bs0 = sm + 2 * ATILE;
    float* Bs1 = sm + 2 * ATILE + BTILE;

    const int nc = K >> 5;
    float4 rA[4], rB[BLD];

    auto fetch = [&](int c) {
        int k0 = c << 5;
#pragma unroll
        for (int j = 0; j < 4; j++) {
            int i = tid + j * 256;
            int r = i >> 3, c4 = i & 7;
            rA[j] = *(const float4*)(Ab + (size_t)r * lda + k0 + c4 * 4);
        }
#pragma unroll
        for (int j = 0; j < BLD; j++) {
            int i = tid + j * 256;
            int r = i >> 3, c4 = i & 7;
            rB[j] = *(const float4*)(Bb + (size_t)r * ldb + k0 + c4 * 4);
        }
    };
    auto stash = [&](float* Ad, float* Bd) {
#pragma unroll
        for (int j = 0; j < 4; j++) {
            int i = tid + j * 256;
            int r = i >> 3, c4 = i & 7;
            float* d = Ad + r * ST + c4 * 4;
            d[0] = tf32r(rA[j].x); d[1] = tf32r(rA[j].y);
            d[2] = tf32r(rA[j].z); d[3] = tf32r(rA[j].w);
        }
#pragma unroll
        for (int j = 0; j < BLD; j++) {
            int i = tid + j * 256;
            int r = i >> 3, c4 = i & 7;
            float* d = Bd + r * ST + c4 * 4;
            d[0] = tf32r(rB[j].x); d[1] = tf32r(rB[j].y);
            d[2] = tf32r(rB[j].z); d[3] = tf32r(rB[j].w);
        }
    };

    fetch(0);
    stash(As0, Bs0);
    __syncthreads();

    for (int c = 0; c < nc; c++) {
        float* Ac = (c & 1) ? As1 : As0;
        float* Bc = (c & 1) ? Bs1 : Bs0;
        if (c + 1 < nc) fetch(c + 1);

#pragma unroll
        for (int ks = 0; ks < 4; ks++) {
            int kb = ks * 8 + (lane & 3);
            uint32_t af[2][4];
            int ar = warp_m * 32 + (lane >> 2);
#pragma unroll
            for (int mt = 0; mt < 2; mt++) {
                const float* ap = Ac + (ar + mt * 16) * ST + kb;
                af[mt][0] = __float_as_uint(ap[0]);
                af[mt][1] = __float_as_uint(ap[8 * ST]);
                af[mt][2] = __float_as_uint(ap[4]);
                af[mt][3] = __float_as_uint(ap[8 * ST + 4]);
            }
            uint32_t bf[NT][2];
            int br = warp_n * (NT * 8) + (lane >> 2);
#pragma unroll
            for (int nt = 0; nt < NT; nt++) {
                const float* bp = Bc + (br + nt * 8) * ST + kb;
                bf[nt][0] = __float_as_uint(bp[0]);
                bf[nt][1] = __float_as_uint(bp[4]);
            }
#pragma unroll
            for (int mt = 0; mt < 2; mt++)
#pragma unroll
                for (int nt = 0; nt < NT; nt++)
                    mma_tf32(acc[mt][nt], af[mt], bf[nt]);
        }

        if (c + 1 < nc) stash((c & 1) ? As0 : As1, (c & 1) ? Bs0 : Bs1);
        __syncthreads();
    }
}

struct GP {
    const float* A; long long lda, aB, aH;
    const float* B; long long ldb, bB, bH;
    float* C;       long long ldc, cB, cH;
    const float* bias;
    const int* tok;
    int K, relu, causal;
};

// MODE 0: C = A*B^T (+bias)(+relu);  MODE 1: masked scaled scores;  MODE 2: transposed store
template <int MODE, int BN>
__global__ __launch_bounds__(256, 2) void gemm_std(GP p) {
    extern __shared__ float sm[];
    constexpr int NT = BN / 16;
    int tid = threadIdx.x, lane = tid & 31, wid = tid >> 5;
    int warp_m = wid & 3, warp_n = wid >> 2;
    int b = blockIdx.z / NH, h = blockIdx.z % NH;

    const float* Ab = p.A + (size_t)b * p.aB + (size_t)h * p.aH +
                      (size_t)(blockIdx.y * 128) * p.lda;
    const float* Bb = p.B + (size_t)b * p.bB + (size_t)h * p.bH +
                      (size_t)(blockIdx.x * BN) * p.ldb;

    float acc[2][NT][4];
#pragma unroll
    for (int mt = 0; mt < 2; mt++)
#pragma unroll
        for (int nt = 0; nt < NT; nt++)
#pragma unroll
            for (int i = 0; i < 4; i++) acc[mt][nt][i] = 0.f;

    gemm_core<BN>(Ab, p.lda, Bb, p.ldb, p.K, sm, tid, lane, warp_m, warp_n, acc);

    float* Cb = p.C + (size_t)b * p.cB + (size_t)h * p.cH;
    const int* tokb = p.tok ? (p.tok + b * 512) : nullptr;
    int mbase = blockIdx.y * 128 + warp_m * 32 + (lane >> 2);
    int nbase = blockIdx.x * BN + warp_n * (NT * 8) + (lane & 3) * 2;

#pragma unroll
    for (int mt = 0; mt < 2; mt++) {
#pragma unroll
        for (int nt = 0; nt < NT; nt++) {
            int n = nbase + nt * 8;
#pragma unroll
            for (int hf = 0; hf < 2; hf++) {
                int m = mbase + mt * 16 + hf * 8;
                float v0 = acc[mt][nt][hf * 2];
                float v1 = acc[mt][nt][hf * 2 + 1];
                if (MODE == 0) {
                    if (p.bias) { v0 += p.bias[n]; v1 += p.bias[n + 1]; }
                    if (p.relu) { v0 = fmaxf(v0, 0.f); v1 = fmaxf(v1, 0.f); }
                    float2 o = {v0, v1};
                    *(float2*)(Cb + (size_t)m * p.ldc + n) = o;
                } else if (MODE == 1) {
                    v0 *= 0.125f; v1 *= 0.125f;
                    if (tokb[n] == 0 || (p.causal && n > m)) v0 = -1e9f;
                    if (tokb[n + 1] == 0 || (p.causal && n + 1 > m)) v1 = -1e9f;
                    float2 o = {v0, v1};
                    *(float2*)(Cb + (size_t)m * p.ldc + n) = o;
                } else {
                    if (p.bias) { v0 += p.bias[n]; v1 += p.bias[n + 1]; }
                    Cb[(size_t)n * p.ldc + m] = v0;
                    Cb[(size_t)(n + 1) * p.ldc + m] = v1;
                }
            }
        }
    }
}

// ---------------- fused QKV projection ----------------
// grid (12, 32): blockIdx.x>>2 selects {Q, K, V}; V stores transposed into vt.
struct QKVP {
    const float* A[3];
    const float* W[3];
    const float* bias[3];
    float* C[3];
};

__global__ __launch_bounds__(256, 2) void gemm_qkv(QKVP p) {
    extern __shared__ float sm[];
    constexpr int BN = 128, NT = 8;
    int tid = threadIdx.x, lane = tid & 31, wid = tid >> 5;
    int warp_m = wid & 3, warp_n = wid >> 2;
    int sel = blockIdx.x >> 2;
    int nblk = blockIdx.x & 3;

    const float* Ab = p.A[sel] + (size_t)(blockIdx.y * 128) * DIM;
    const float* Bb = p.W[sel] + (size_t)(nblk * BN) * DIM;

    float acc[2][NT][4];
#pragma unroll
    for (int mt = 0; mt < 2; mt++)
#pragma unroll
        for (int nt = 0; nt < NT; nt++)
#pragma unroll
            for (int i = 0; i < 4; i++) acc[mt][nt][i] = 0.f;

    gemm_core<BN>(Ab, DIM, Bb, DIM, DIM, sm, tid, lane, warp_m, warp_n, acc);

    const float* bias = p.bias[sel];
    float* Cb = p.C[sel];
    int mbase = blockIdx.y * 128 + warp_m * 32 + (lane >> 2);
    int nbase = nblk * BN + warp_n * (NT * 8) + (lane & 3) * 2;

#pragma unroll
    for (int mt = 0; mt < 2; mt++) {
#pragma unroll
        for (int nt = 0; nt < NT; nt++) {
            int n = nbase + nt * 8;
#pragma unroll
            for (int hf = 0; hf < 2; hf++) {
                int m = mbase + mt * 16 + hf * 8;
                float v0 = acc[mt][nt][hf * 2] + bias[n];
                float v1 = acc[mt][nt][hf * 2 + 1] + bias[n + 1];
                if (sel < 2) {
                    float2 o = {v0, v1};
                    *(float2*)(Cb + (size_t)m * DIM + n) = o;
                } else {
                    Cb[(size_t)n * (BB * LDQ) + m] = v0;
                    Cb[(size_t)(n + 1) * (BB * LDQ) + m] = v1;
                }
            }
        }
    }
}

// ---------------- reductions ----------------
__device__ __forceinline__ float blockReduceSum256(float v, float* red) {
    int lane = threadIdx.x & 31, wid = threadIdx.x >> 5;
#pragma unroll
    for (int o = 16; o > 0; o >>= 1) v += __shfl_xor_sync(0xffffffffu, v, o);
    if (lane == 0) red[wid] = v;
    __syncthreads();
    float r = 0.f;
    if (threadIdx.x < 8) r = red[threadIdx.x];
    if (wid == 0) {
#pragma unroll
        for (int o = 4; o > 0; o >>= 1) r += __shfl_xor_sync(0xffu, r, o);
        if (lane == 0) red[0] = r;
    }
    __syncthreads();
    float out = red[0];
    __syncthreads();
    return out;
}

__device__ __forceinline__ float blockReduceMax256(float v, float* red) {
    int lane = threadIdx.x & 31, wid = threadIdx.x >> 5;
#pragma unroll
    for (int o = 16; o > 0; o >>= 1) v = fmaxf(v, __shfl_xor_sync(0xffffffffu, v, o));
    if (lane == 0) red[wid] = v;
    __syncthreads();
    float r = -1e30f;
    if (threadIdx.x < 8) r = red[threadIdx.x];
    if (wid == 0) {
#pragma unroll
        for (int o = 4; o > 0; o >>= 1) r = fmaxf(r, __shfl_xor_sync(0xffu, r, o));
        if (lane == 0) red[0] = r;
    }
    __syncthreads();
    float out = red[0];
    __syncthreads();
    return out;
}

// ---------------- embedding + sinusoidal position ----------------
__global__ __launch_bounds__(256) void embed_kernel(const int* __restrict__ dec,
                                                    const float* __restrict__ emb,
                                                    float* __restrict__ x) {
    int idx = blockIdx.x * 256 + threadIdx.x;
    if (idx >= BB * LDQ * DIM) return;
    int d = idx & (DIM - 1);
    int bl = idx / DIM;
    int l = bl & (LDQ - 1);
    int tok = dec[bl];
    double pos = (double)(l + 1);
    int jhalf = d >> 1;
    double denom = pow(10000.0, (double)(2 * jhalf) / (double)DIM);
    double a = pos / denom;
    float pe = ((d & 1) == 0) ? (float)sin(a) : (float)cos(a);
    x[idx] = emb[(size_t)tok * DIM + d] + pe;
}

// ---------------- row softmax over 512 (in place) ----------------
__global__ __launch_bounds__(256) void softmax_rows(float* __restrict__ S) {
    float* row = S + (size_t)blockIdx.x * 512;
    int t = threadIdx.x;
    __shared__ float red[32];
    float v0 = row[t], v1 = row[t + 256];
    float m = blockReduceMax256(fmaxf(v0, v1), red);
    float e0 = expf(v0 - m), e1 = expf(v1 - m);
    float s = blockReduceSum256(e0 + e1, red);
    float inv = 1.f / s;
    row[t] = e0 * inv;
    row[t + 256] = e1 * inv;
}

// ---------------- residual add + layernorm ----------------
__global__ __launch_bounds__(256) void add_ln(const float* __restrict__ A,
                                              const float* __restrict__ R,
                                              const float* __restrict__ g,
                                              const float* __restrict__ be,
                                              float* __restrict__ out) {
    int row = blockIdx.x;
    int t = threadIdx.x;
    __shared__ float red[32];
    const float* a = A + (size_t)row * DIM;
    const float* r = R + (size_t)row * DIM;
    float x0 = a[t] + r[t];
    float x1 = a[t + 256] + r[t + 256];
    float s = blockReduceSum256(x0 + x1, red);
    float mean = s * (1.f / 512.f);
    float d0 = x0 - mean, d1 = x1 - mean;
    float s2 = blockReduceSum256(d0 * d0 + d1 * d1, red);
    float inv = rsqrtf(s2 * (1.f / 512.f) + 1e-5f);
    out[(size_t)row * DIM + t] = d0 * inv * g[t] + be[t];
    out[(size_t)row * DIM + t + 256] = d1 * inv * g[t + 256] + be[t + 256];
}

// ---------------- host orchestration ----------------
#define SMEM128 (2 * (128 + 128) * 36 * 4)
#define SMEM64  (2 * (128 + 64) * 36 * 4)

extern "C" void kernel_launch(void* const* d_in, const int* in_sizes, int n_in,
                              void* d_out, int out_size) {
    const int* dec = (const int*)d_in[0];
    const int* enc = (const int*)d_in[1];
    const float* enc_out = (const float*)d_in[2];
    const float* emb = (const float*)d_in[3];

    bool dict_order = (in_sizes[5] == NLAY * DIM * DIM);
    int iwq[2], iwk[2], iwv[2], iwo[2], ibq[2], ibk[2], ibv[2], ibo[2], ig[2], ib[2];
    for (int p = 0; p < 2; p++) {
        int base = 4 + p * 10;
        if (dict_order) {
            iwq[p] = base + 0; iwk[p] = base + 1; iwv[p] = base + 2; iwo[p] = base + 3;
            ibq[p] = base + 4; ibk[p] = base + 5; ibv[p] = base + 6; ibo[p] = base + 7;
            ig[p] = base + 8; ib[p] = base + 9;
        } else {
            iwq[p] = base + 0; ibq[p] = base + 1; iwk[p] = base + 2; ibk[p] = base + 3;
            iwv[p] = base + 4; ibv[p] = base + 5; iwo[p] = base + 6; ibo[p] = base + 7;
            ig[p] = base + 8; ib[p] = base + 9;
        }
    }
    const float* ffn_w1 = (const float*)d_in[24];
    const float* ffn_b1 = (const float*)d_in[25];
    const float* ffn_w2 = (const float*)d_in[26];
    const float* ffn_b2 = (const float*)d_in[27];
    const float* ffn_g = (const float*)d_in[28];
    const float* ffn_bb = (const float*)d_in[29];

    float *x, *q, *k, *vt, *ctxp, *proj, *ffh;
    cudaGetSymbolAddress((void**)&x, g_x);
    cudaGetSymbolAddress((void**)&q, g_q);
    cudaGetSymbolAddress((void**)&k, g_k);
    cudaGetSymbolAddress((void**)&vt, g_vt);
    cudaGetSymbolAddress((void**)&ctxp, g_ctx);
    cudaGetSymbolAddress((void**)&proj, g_proj);
    cudaGetSymbolAddress((void**)&ffh, g_ffh);

    cudaFuncSetAttribute(gemm_qkv, cudaFuncAttributeMaxDynamicSharedMemorySize, SMEM128);
    cudaFuncSetAttribute(gemm_std<0, 128>, cudaFuncAttributeMaxDynamicSharedMemorySize, SMEM128);
    cudaFuncSetAttribute(gemm_std<1, 128>, cudaFuncAttributeMaxDynamicSharedMemorySize, SMEM128);
    cudaFuncSetAttribute(gemm_std<0, 64>, cudaFuncAttributeMaxDynamicSharedMemorySize, SMEM64);

    float* out = (float*)d_out;
    const size_t XSZ = (size_t)BB * LDQ * DIM;
    const size_t AW = (size_t)BB * NH * LDQ * LDQ;
    float* sa_base = out + XSZ;
    float* ca_base = out + XSZ + (size_t)NLAY * AW;

    const int M = BB * LDQ;                     // 4096
    const long long LL = (long long)LDQ * LDQ;  // per-(b,h) score block

    embed_kernel<<<(BB * LDQ * DIM + 255) / 256, 256>>>(dec, emb, x);

    for (int l = 0; l < NLAY; l++) {
        size_t wofs = (size_t)l * DIM * DIM;
        size_t bofs = (size_t)l * DIM;

        for (int p = 0; p < 2; p++) {
            const float* wq = (const float*)d_in[iwq[p]] + wofs;
            const float* wk = (const float*)d_in[iwk[p]] + wofs;
            const float* wv = (const float*)d_in[iwv[p]] + wofs;
            const float* wo = (const float*)d_in[iwo[p]] + wofs;
            const float* bq = (const float*)d_in[ibq[p]] + bofs;
            const float* bk = (const float*)d_in[ibk[p]] + bofs;
            const float* bv = (const float*)d_in[ibv[p]] + bofs;
            const float* bo = (const float*)d_in[ibo[p]] + bofs;
            const float* gg = (const float*)d_in[ig[p]] + bofs;
            const float* bt = (const float*)d_in[ib[p]] + bofs;

            const float* kv_src = (p == 0) ? x : enc_out;
            const int* tok = (p == 0) ? dec : enc;
            int causal = (p == 0) ? 1 : 0;
            float* S = ((p == 0) ? sa_base : ca_base) + (size_t)l * AW;

            // fused Q/K/V projections
            QKVP qp;
            qp.A[0] = x;  qp.A[1] = kv_src; qp.A[2] = kv_src;
            qp.W[0] = wq; qp.W[1] = wk;     qp.W[2] = wv;
            qp.bias[0] = bq; qp.bias[1] = bk; qp.bias[2] = bv;
            qp.C[0] = q;  qp.C[1] = k;      qp.C[2] = vt;
            gemm_qkv<<<dim3(12, 32), 256, SMEM128>>>(qp);

            GP gp;
            // scores
            gp = GP{q, DIM, LL, 64, k, DIM, LL, 64, S, LDQ, NH * LL, LL,
                    nullptr, tok, 64, 0, causal};
            gemm_std<1, 128><<<dim3(4, 4, BB * NH), 256, SMEM128>>>(gp);
            softmax_rows<<<BB * NH * LDQ, 256>>>(S);
            // ctx[b,q,h*64+d] = sum_k S[b,h,q,k] * vt[h*64+d][b*512+k]
            gp = GP{S, LDQ, NH * LL, LL, vt, M, LDQ, 64LL * M, ctxp, DIM, LL, 64,
                    nullptr, nullptr, 512, 0, 0};
            gemm_std<0, 64><<<dim3(1, 4, BB * NH), 256, SMEM64>>>(gp);
            // out proj (128x64 tiles -> 256 blocks)
            gp = GP{ctxp, DIM, 0, 0, wo, DIM, 0, 0, proj, DIM, 0, 0, bo, nullptr, DIM, 0, 0};
            gemm_std<0, 64><<<dim3(8, 32, 1), 256, SMEM64>>>(gp);
            add_ln<<<M, 256>>>(proj, x, gg, bt, x);
        }

        // FFN
        GP gp;
        gp = GP{x, DIM, 0, 0, ffn_w1 + (size_t)l * FFD * DIM, DIM, 0, 0,
                ffh, FFD, 0, 0, ffn_b1 + (size_t)l * FFD, nullptr, DIM, 1, 0};
        gemm_std<0, 128><<<dim3(16, 32, 1), 256, SMEM128>>>(gp);
        gp = GP{ffh, FFD, 0, 0, ffn_w2 + (size_t)l * DIM * FFD, FFD, 0, 0,
                proj, DIM, 0, 0, ffn_b2 + bofs, nullptr, FFD, 0, 0};
        gemm_std<0, 64><<<dim3(8, 32, 1), 256, SMEM64>>>(gp);
        float* lnout = (l == NLAY - 1) ? out : x;
        add_ln<<<M, 256>>>(proj, x, ffn_g + bofs, ffn_bb + bofs, lnout);
    }
}

// round 5
// speedup vs baseline: 3.3179x; 1.0855x over previous
#include <cuda_runtime.h>
#include <cstdint>
#include <math.h>

#define BB 8
#define LDQ 512
#define DIM 512
#define NH 8
#define FFD 2048
#define NLAY 6

// ---------------- scratch (static device globals; no allocation) ----------------
__device__ float g_x[BB * LDQ * DIM];
__device__ float g_q[BB * LDQ * DIM];
__device__ float g_k[BB * LDQ * DIM];
__device__ float g_vt[DIM * BB * LDQ];   // transposed V: [d_global][token]
__device__ float g_ctx[BB * LDQ * DIM];
__device__ float g_proj[BB * LDQ * DIM];
__device__ float g_ffh[BB * LDQ * FFD];

// ---------------- small helpers ----------------
__device__ __forceinline__ float tf32r(float x) {
    uint32_t u;
    asm("cvt.rna.tf32.f32 %0, %1;" : "=r"(u) : "f"(x));
    return __uint_as_float(u);
}

__device__ __forceinline__ void mma_tf32(float* c, const uint32_t* a, const uint32_t* b) {
    asm volatile(
        "mma.sync.aligned.m16n8k8.row.col.f32.tf32.tf32.f32 "
        "{%0,%1,%2,%3}, {%4,%5,%6,%7}, {%8,%9}, {%0,%1,%2,%3};"
        : "+f"(c[0]), "+f"(c[1]), "+f"(c[2]), "+f"(c[3])
        : "r"(a[0]), "r"(a[1]), "r"(a[2]), "r"(a[3]), "r"(b[0]), "r"(b[1]));
}

// ---------------- core: 128 x BN tile, K-chunk 32, double-buffered ----------------
template <int BN>
__device__ __forceinline__ void gemm_core(const float* __restrict__ Ab, long long lda,
                                          const float* __restrict__ Bb, long long ldb,
                                          int K, float* sm, int tid, int lane,
                                          int warp_m, int warp_n,
                                          float (&acc)[2][BN / 16][4]) {
    constexpr int ST = 36;
    constexpr int ATILE = 128 * ST;
    constexpr int BTILE = BN * ST;
    constexpr int NT = BN / 16;
    constexpr int BLD = BN / 32;

    float* As0 = sm;
    float* As1 = sm + ATILE;
    float* Bs0 = sm + 2 * ATILE;
    float* Bs1 = sm + 2 * ATILE + BTILE;

    const int nc = K >> 5;
    float4 rA[4], rB[BLD];

    auto fetch = [&](int c) {
        int k0 = c << 5;
#pragma unroll
        for (int j = 0; j < 4; j++) {
            int i = tid + j * 256;
            int r = i >> 3, c4 = i & 7;
            rA[j] = *(const float4*)(Ab + (size_t)r * lda + k0 + c4 * 4);
        }
#pragma unroll
        for (int j = 0; j < BLD; j++) {
            int i = tid + j * 256;
            int r = i >> 3, c4 = i & 7;
            rB[j] = *(const float4*)(Bb + (size_t)r * ldb + k0 + c4 * 4);
        }
    };
    auto stash = [&](float* Ad, float* Bd) {
#pragma unroll
        for (int j = 0; j < 4; j++) {
            int i = tid + j * 256;
            int r = i >> 3, c4 = i & 7;
            float* d = Ad + r * ST + c4 * 4;
            d[0] = tf32r(rA[j].x); d[1] = tf32r(rA[j].y);
            d[2] = tf32r(rA[j].z); d[3] = tf32r(rA[j].w);
        }
#pragma unroll
        for (int j = 0; j < BLD; j++) {
            int i = tid + j * 256;
            int r = i >> 3, c4 = i & 7;
            float* d = Bd + r * ST + c4 * 4;
            d[0] = tf32r(rB[j].x); d[1] = tf32r(rB[j].y);
            d[2] = tf32r(rB[j].z); d[3] = tf32r(rB[j].w);
        }
    };

    fetch(0);
    stash(As0, Bs0);
    __syncthreads();

    for (int c = 0; c < nc; c++) {
        float* Ac = (c & 1) ? As1 : As0;
        float* Bc = (c & 1) ? Bs1 : Bs0;
        if (c + 1 < nc) fetch(c + 1);

#pragma unroll
        for (int ks = 0; ks < 4; ks++) {
            int kb = ks * 8 + (lane & 3);
            uint32_t af[2][4];
            int ar = warp_m * 32 + (lane >> 2);
#pragma unroll
            for (int mt = 0; mt < 2; mt++) {
                const float* ap = Ac + (ar + mt * 16) * ST + kb;
                af[mt][0] = __float_as_uint(ap[0]);
                af[mt][1] = __float_as_uint(ap[8 * ST]);
                af[mt][2] = __float_as_uint(ap[4]);
                af[mt][3] = __float_as_uint(ap[8 * ST + 4]);
            }
            uint32_t bf[NT][2];
            int br = warp_n * (NT * 8) + (lane >> 2);
#pragma unroll
            for (int nt = 0; nt < NT; nt++) {
                const float* bp = Bc + (br + nt * 8) * ST + kb;
                bf[nt][0] = __float_as_uint(bp[0]);
                bf[nt][1] = __float_as_uint(bp[4]);
            }
#pragma unroll
            for (int mt = 0; mt < 2; mt++)
#pragma unroll
                for (int nt = 0; nt < NT; nt++)
                    mma_tf32(acc[mt][nt], af[mt], bf[nt]);
        }

        if (c + 1 < nc) stash((c & 1) ? As0 : As1, (c & 1) ? Bs0 : Bs1);
        __syncthreads();
    }
}

struct GP {
    const float* A; long long lda, aB, aH;
    const float* B; long long ldb, bB, bH;
    float* C;       long long ldc, cB, cH;
    const float* bias;
    const int* tok;
    int K, relu, causal;
};

// MODE 0: C = A*B^T (+bias)(+relu);  MODE 2: transposed store
template <int MODE, int BN>
__global__ __launch_bounds__(256, 2) void gemm_std(GP p) {
    extern __shared__ float sm[];
    constexpr int NT = BN / 16;
    int tid = threadIdx.x, lane = tid & 31, wid = tid >> 5;
    int warp_m = wid & 3, warp_n = wid >> 2;
    int b = blockIdx.z / NH, h = blockIdx.z % NH;

    const float* Ab = p.A + (size_t)b * p.aB + (size_t)h * p.aH +
                      (size_t)(blockIdx.y * 128) * p.lda;
    const float* Bb = p.B + (size_t)b * p.bB + (size_t)h * p.bH +
                      (size_t)(blockIdx.x * BN) * p.ldb;

    float acc[2][NT][4];
#pragma unroll
    for (int mt = 0; mt < 2; mt++)
#pragma unroll
        for (int nt = 0; nt < NT; nt++)
#pragma unroll
            for (int i = 0; i < 4; i++) acc[mt][nt][i] = 0.f;

    gemm_core<BN>(Ab, p.lda, Bb, p.ldb, p.K, sm, tid, lane, warp_m, warp_n, acc);

    float* Cb = p.C + (size_t)b * p.cB + (size_t)h * p.cH;
    int mbase = blockIdx.y * 128 + warp_m * 32 + (lane >> 2);
    int nbase = blockIdx.x * BN + warp_n * (NT * 8) + (lane & 3) * 2;

#pragma unroll
    for (int mt = 0; mt < 2; mt++) {
#pragma unroll
        for (int nt = 0; nt < NT; nt++) {
            int n = nbase + nt * 8;
#pragma unroll
            for (int hf = 0; hf < 2; hf++) {
                int m = mbase + mt * 16 + hf * 8;
                float v0 = acc[mt][nt][hf * 2];
                float v1 = acc[mt][nt][hf * 2 + 1];
                if (MODE == 0) {
                    if (p.bias) { v0 += p.bias[n]; v1 += p.bias[n + 1]; }
                    if (p.relu) { v0 = fmaxf(v0, 0.f); v1 = fmaxf(v1, 0.f); }
                    float2 o = {v0, v1};
                    *(float2*)(Cb + (size_t)m * p.ldc + n) = o;
                } else {
                    if (p.bias) { v0 += p.bias[n]; v1 += p.bias[n + 1]; }
                    Cb[(size_t)n * p.ldc + m] = v0;
                    Cb[(size_t)(n + 1) * p.ldc + m] = v1;
                }
            }
        }
    }
}

// ---------------- fused QKV projection ----------------
struct QKVP {
    const float* A[3];
    const float* W[3];
    const float* bias[3];
    float* C[3];
};

__global__ __launch_bounds__(256, 2) void gemm_qkv(QKVP p) {
    extern __shared__ float sm[];
    constexpr int BN = 128, NT = 8;
    int tid = threadIdx.x, lane = tid & 31, wid = tid >> 5;
    int warp_m = wid & 3, warp_n = wid >> 2;
    int sel = blockIdx.x >> 2;
    int nblk = blockIdx.x & 3;

    const float* Ab = p.A[sel] + (size_t)(blockIdx.y * 128) * DIM;
    const float* Bb = p.W[sel] + (size_t)(nblk * BN) * DIM;

    float acc[2][NT][4];
#pragma unroll
    for (int mt = 0; mt < 2; mt++)
#pragma unroll
        for (int nt = 0; nt < NT; nt++)
#pragma unroll
            for (int i = 0; i < 4; i++) acc[mt][nt][i] = 0.f;

    gemm_core<BN>(Ab, DIM, Bb, DIM, DIM, sm, tid, lane, warp_m, warp_n, acc);

    const float* bias = p.bias[sel];
    float* Cb = p.C[sel];
    int mbase = blockIdx.y * 128 + warp_m * 32 + (lane >> 2);
    int nbase = nblk * BN + warp_n * (NT * 8) + (lane & 3) * 2;

#pragma unroll
    for (int mt = 0; mt < 2; mt++) {
#pragma unroll
        for (int nt = 0; nt < NT; nt++) {
            int n = nbase + nt * 8;
#pragma unroll
            for (int hf = 0; hf < 2; hf++) {
                int m = mbase + mt * 16 + hf * 8;
                float v0 = acc[mt][nt][hf * 2] + bias[n];
                float v1 = acc[mt][nt][hf * 2 + 1] + bias[n + 1];
                if (sel < 2) {
                    float2 o = {v0, v1};
                    *(float2*)(Cb + (size_t)m * DIM + n) = o;
                } else {
                    Cb[(size_t)n * (BB * LDQ) + m] = v0;
                    Cb[(size_t)(n + 1) * (BB * LDQ) + m] = v1;
                }
            }
        }
    }
}

// ---------------- fused scores + mask + softmax ----------------
// Block: 32 q-rows x 512 keys for one (b,h). 8 warps, each owns a 64-key chunk.
// Writes normalized softmax weights directly to S.
#define STQ 68
#define SS_Q_FLOATS (32 * STQ)
#define SS_K_FLOATS (512 * STQ)
#define SS_SMEM_BYTES ((SS_Q_FLOATS + SS_K_FLOATS) * 4 + 512 * 4 + 32 * 8 * 4 + 32 * 4)

struct SSP {
    const float* Q;   // [B*LDQ, DIM]
    const float* K;   // [B*LDQ, DIM]
    const int* tok;   // [B, 512]
    float* S;         // [B, NH, LDQ, 512]
    int causal;
};

__global__ __launch_bounds__(256) void scores_softmax(SSP p) {
    extern __shared__ float sm[];
    float* sQ = sm;
    float* sK = sm + SS_Q_FLOATS;
    int* stok = (int*)(sm + SS_Q_FLOATS + SS_K_FLOATS);
    float* red = (float*)(stok + 512);        // [32][8]
    float* rowstat = red + 32 * 8;            // [32]

    int tid = threadIdx.x, lane = tid & 31, w = tid >> 5;
    int bh = blockIdx.y;
    int b = bh / NH, h = bh % NH;
    int q0 = blockIdx.x * 32;

    const float* Qb = p.Q + (size_t)b * LDQ * DIM + (size_t)h * 64 + (size_t)q0 * DIM;
    const float* Kb = p.K + (size_t)b * LDQ * DIM + (size_t)h * 64;
    const int* tokb = p.tok + b * 512;

    // load Q (32x64) and K (512x64) tiles, tf32-rounded
#pragma unroll
    for (int j = 0; j < 2; j++) {
        int i = tid + j * 256;               // 512 float4 total
        int r = i >> 4, c4 = i & 15;
        float4 v = *(const float4*)(Qb + (size_t)r * DIM + c4 * 4);
        float* d = sQ + r * STQ + c4 * 4;
        d[0] = tf32r(v.x); d[1] = tf32r(v.y); d[2] = tf32r(v.z); d[3] = tf32r(v.w);
    }
#pragma unroll
    for (int j = 0; j < 32; j++) {
        int i = tid + j * 256;               // 8192 float4 total
        int r = i >> 4, c4 = i & 15;
        float4 v = *(const float4*)(Kb + (size_t)r * DIM + c4 * 4);
        float* d = sK + r * STQ + c4 * 4;
        d[0] = tf32r(v.x); d[1] = tf32r(v.y); d[2] = tf32r(v.z); d[3] = tf32r(v.w);
    }
    if (tid < 256) {
        stok[tid] = tokb[tid];
        stok[tid + 256] = tokb[tid + 256];
    }
    __syncthreads();

    // MMA: 32 x 512, K=64
    float acc[2][8][4];
#pragma unroll
    for (int mt = 0; mt < 2; mt++)
#pragma unroll
        for (int nt = 0; nt < 8; nt++)
#pragma unroll
            for (int i = 0; i < 4; i++) acc[mt][nt][i] = 0.f;

#pragma unroll
    for (int ks = 0; ks < 8; ks++) {
        int kb = ks * 8 + (lane & 3);
        uint32_t af[2][4];
        int ar = lane >> 2;
#pragma unroll
        for (int mt = 0; mt < 2; mt++) {
            const float* ap = sQ + (ar + mt * 16) * STQ + kb;
            af[mt][0] = __float_as_uint(ap[0]);
            af[mt][1] = __float_as_uint(ap[8 * STQ]);
            af[mt][2] = __float_as_uint(ap[4]);
            af[mt][3] = __float_as_uint(ap[8 * STQ + 4]);
        }
        uint32_t bf[8][2];
        int br = w * 64 + (lane >> 2);
#pragma unroll
        for (int nt = 0; nt < 8; nt++) {
            const float* bp = sK + (br + nt * 8) * STQ + kb;
            bf[nt][0] = __float_as_uint(bp[0]);
            bf[nt][1] = __float_as_uint(bp[4]);
        }
#pragma unroll
        for (int mt = 0; mt < 2; mt++)
#pragma unroll
            for (int nt = 0; nt < 8; nt++)
                mma_tf32(acc[mt][nt], af[mt], bf[nt]);
    }

    // scale + mask in registers; track per-row max of this thread's 16 vals
    // thread rows: row[mt][hf] = mt*16 + (lane>>2) + hf*8
    float lmax[2][2] = {{-1e30f, -1e30f}, {-1e30f, -1e30f}};
#pragma unroll
    for (int mt = 0; mt < 2; mt++) {
#pragma unroll
        for (int nt = 0; nt < 8; nt++) {
#pragma unroll
            for (int j = 0; j < 4; j++) {
                int hf = j >> 1;
                int col = w * 64 + nt * 8 + (lane & 3) * 2 + (j & 1);
                int row = mt * 16 + (lane >> 2) + hf * 8;
                float v = acc[mt][nt][j] * 0.125f;
                bool msk = (stok[col] == 0) || (p.causal && col > q0 + row);
                v = msk ? -1e9f : v;
                acc[mt][nt][j] = v;
                lmax[mt][hf] = fmaxf(lmax[mt][hf], v);
            }
        }
    }
    // quad reduce (lanes lane&3), then cross-warp via smem
#pragma unroll
    for (int mt = 0; mt < 2; mt++)
#pragma unroll
        for (int hf = 0; hf < 2; hf++) {
            float v = lmax[mt][hf];
            v = fmaxf(v, __shfl_xor_sync(0xffffffffu, v, 1));
            v = fmaxf(v, __shfl_xor_sync(0xffffffffu, v, 2));
            lmax[mt][hf] = v;
        }
    if ((lane & 3) == 0) {
        int r0 = lane >> 2;
        red[(r0) * 8 + w] = lmax[0][0];
        red[(r0 + 8) * 8 + w] = lmax[0][1];
        red[(r0 + 16) * 8 + w] = lmax[1][0];
        red[(r0 + 24) * 8 + w] = lmax[1][1];
    }
    __syncthreads();
    if (tid < 32) {
        float m = red[tid * 8];
#pragma unroll
        for (int i = 1; i < 8; i++) m = fmaxf(m, red[tid * 8 + i]);
        rowstat[tid] = m;
    }
    __syncthreads();

    float rmax[2][2];
#pragma unroll
    for (int mt = 0; mt < 2; mt++)
#pragma unroll
        for (int hf = 0; hf < 2; hf++)
            rmax[mt][hf] = rowstat[mt * 16 + (lane >> 2) + hf * 8];
    __syncthreads();

    // exp + sum
    float lsum[2][2] = {{0.f, 0.f}, {0.f, 0.f}};
#pragma unroll
    for (int mt = 0; mt < 2; mt++)
#pragma unroll
        for (int nt = 0; nt < 8; nt++)
#pragma unroll
            for (int j = 0; j < 4; j++) {
                int hf = j >> 1;
                float e = expf(acc[mt][nt][j] - rmax[mt][hf]);
                acc[mt][nt][j] = e;
                lsum[mt][hf] += e;
            }
#pragma unroll
    for (int mt = 0; mt < 2; mt++)
#pragma unroll
        for (int hf = 0; hf < 2; hf++) {
            float v = lsum[mt][hf];
            v += __shfl_xor_sync(0xffffffffu, v, 1);
            v += __shfl_xor_sync(0xffffffffu, v, 2);
            lsum[mt][hf] = v;
        }
    if ((lane & 3) == 0) {
        int r0 = lane >> 2;
        red[(r0) * 8 + w] = lsum[0][0];
        red[(r0 + 8) * 8 + w] = lsum[0][1];
        red[(r0 + 16) * 8 + w] = lsum[1][0];
        red[(r0 + 24) * 8 + w] = lsum[1][1];
    }
    __syncthreads();
    if (tid < 32) {
        float s = 0.f;
#pragma unroll
        for (int i = 0; i < 8; i++) s += red[tid * 8 + i];
        rowstat[tid] = 1.f / s;
    }
    __syncthreads();

    float rinv[2][2];
#pragma unroll
    for (int mt = 0; mt < 2; mt++)
#pragma unroll
        for (int hf = 0; hf < 2; hf++)
            rinv[mt][hf] = rowstat[mt * 16 + (lane >> 2) + hf * 8];

    // write normalized weights
    float* Sb = p.S + (size_t)bh * LDQ * 512;
#pragma unroll
    for (int mt = 0; mt < 2; mt++)
#pragma unroll
        for (int nt = 0; nt < 8; nt++)
#pragma unroll
            for (int hf = 0; hf < 2; hf++) {
                int row = q0 + mt * 16 + (lane >> 2) + hf * 8;
                int col = w * 64 + nt * 8 + (lane & 3) * 2;
                float2 o = {acc[mt][nt][hf * 2] * rinv[mt][hf],
                            acc[mt][nt][hf * 2 + 1] * rinv[mt][hf]};
                *(float2*)(Sb + (size_t)row * 512 + col) = o;
            }
}

// ---------------- reductions ----------------
__device__ __forceinline__ float blockReduceSum256(float v, float* red) {
    int lane = threadIdx.x & 31, wid = threadIdx.x >> 5;
#pragma unroll
    for (int o = 16; o > 0; o >>= 1) v += __shfl_xor_sync(0xffffffffu, v, o);
    if (lane == 0) red[wid] = v;
    __syncthreads();
    float r = 0.f;
    if (threadIdx.x < 8) r = red[threadIdx.x];
    if (wid == 0) {
#pragma unroll
        for (int o = 4; o > 0; o >>= 1) r += __shfl_xor_sync(0xffu, r, o);
        if (lane == 0) red[0] = r;
    }
    __syncthreads();
    float out = red[0];
    __syncthreads();
    return out;
}

// ---------------- embedding + sinusoidal position ----------------
__global__ __launch_bounds__(256) void embed_kernel(const int* __restrict__ dec,
                                                    const float* __restrict__ emb,
                                                    float* __restrict__ x) {
    int idx = blockIdx.x * 256 + threadIdx.x;
    if (idx >= BB * LDQ * DIM) return;
    int d = idx & (DIM - 1);
    int bl = idx / DIM;
    int l = bl & (LDQ - 1);
    int tok = dec[bl];
    double pos = (double)(l + 1);
    int jhalf = d >> 1;
    double denom = pow(10000.0, (double)(2 * jhalf) / (double)DIM);
    double a = pos / denom;
    float pe = ((d & 1) == 0) ? (float)sin(a) : (float)cos(a);
    x[idx] = emb[(size_t)tok * DIM + d] + pe;
}

// ---------------- residual add + layernorm ----------------
__global__ __launch_bounds__(256) void add_ln(const float* __restrict__ A,
                                              const float* __restrict__ R,
                                              const float* __restrict__ g,
                                              const float* __restrict__ be,
                                              float* __restrict__ out) {
    int row = blockIdx.x;
    int t = threadIdx.x;
    __shared__ float red[32];
    const float* a = A + (size_t)row * DIM;
    const float* r = R + (size_t)row * DIM;
    float x0 = a[t] + r[t];
    float x1 = a[t + 256] + r[t + 256];
    float s = blockReduceSum256(x0 + x1, red);
    float mean = s * (1.f / 512.f);
    float d0 = x0 - mean, d1 = x1 - mean;
    float s2 = blockReduceSum256(d0 * d0 + d1 * d1, red);
    float inv = rsqrtf(s2 * (1.f / 512.f) + 1e-5f);
    out[(size_t)row * DIM + t] = d0 * inv * g[t] + be[t];
    out[(size_t)row * DIM + t + 256] = d1 * inv * g[t + 256] + be[t + 256];
}

// ---------------- host orchestration ----------------
#define SMEM128 (2 * (128 + 128) * 36 * 4)
#define SMEM64  (2 * (128 + 64) * 36 * 4)

extern "C" void kernel_launch(void* const* d_in, const int* in_sizes, int n_in,
                              void* d_out, int out_size) {
    const int* dec = (const int*)d_in[0];
    const int* enc = (const int*)d_in[1];
    const float* enc_out = (const float*)d_in[2];
    const float* emb = (const float*)d_in[3];

    bool dict_order = (in_sizes[5] == NLAY * DIM * DIM);
    int iwq[2], iwk[2], iwv[2], iwo[2], ibq[2], ibk[2], ibv[2], ibo[2], ig[2], ib[2];
    for (int p = 0; p < 2; p++) {
        int base = 4 + p * 10;
        if (dict_order) {
            iwq[p] = base + 0; iwk[p] = base + 1; iwv[p] = base + 2; iwo[p] = base + 3;
            ibq[p] = base + 4; ibk[p] = base + 5; ibv[p] = base + 6; ibo[p] = base + 7;
            ig[p] = base + 8; ib[p] = base + 9;
        } else {
            iwq[p] = base + 0; ibq[p] = base + 1; iwk[p] = base + 2; ibk[p] = base + 3;
            iwv[p] = base + 4; ibv[p] = base + 5; iwo[p] = base + 6; ibo[p] = base + 7;
            ig[p] = base + 8; ib[p] = base + 9;
        }
    }
    const float* ffn_w1 = (const float*)d_in[24];
    const float* ffn_b1 = (const float*)d_in[25];
    const float* ffn_w2 = (const float*)d_in[26];
    const float* ffn_b2 = (const float*)d_in[27];
    const float* ffn_g = (const float*)d_in[28];
    const float* ffn_bb = (const float*)d_in[29];

    float *x, *q, *k, *vt, *ctxp, *proj, *ffh;
    cudaGetSymbolAddress((void**)&x, g_x);
    cudaGetSymbolAddress((void**)&q, g_q);
    cudaGetSymbolAddress((void**)&k, g_k);
    cudaGetSymbolAddress((void**)&vt, g_vt);
    cudaGetSymbolAddress((void**)&ctxp, g_ctx);
    cudaGetSymbolAddress((void**)&proj, g_proj);
    cudaGetSymbolAddress((void**)&ffh, g_ffh);

    cudaFuncSetAttribute(gemm_qkv, cudaFuncAttributeMaxDynamicSharedMemorySize, SMEM128);
    cudaFuncSetAttribute(gemm_std<0, 128>, cudaFuncAttributeMaxDynamicSharedMemorySize, SMEM128);
    cudaFuncSetAttribute(gemm_std<0, 64>, cudaFuncAttributeMaxDynamicSharedMemorySize, SMEM64);
    cudaFuncSetAttribute(scores_softmax, cudaFuncAttributeMaxDynamicSharedMemorySize, SS_SMEM_BYTES);

    float* out = (float*)d_out;
    const size_t XSZ = (size_t)BB * LDQ * DIM;
    const size_t AW = (size_t)BB * NH * LDQ * LDQ;
    float* sa_base = out + XSZ;
    float* ca_base = out + XSZ + (size_t)NLAY * AW;

    const int M = BB * LDQ;                     // 4096
    const long long LL = (long long)LDQ * LDQ;  // per-(b,h) score block

    embed_kernel<<<(BB * LDQ * DIM + 255) / 256, 256>>>(dec, emb, x);

    for (int l = 0; l < NLAY; l++) {
        size_t wofs = (size_t)l * DIM * DIM;
        size_t bofs = (size_t)l * DIM;

        for (int p = 0; p < 2; p++) {
            const float* wq = (const float*)d_in[iwq[p]] + wofs;
            const float* wk = (const float*)d_in[iwk[p]] + wofs;
            const float* wv = (const float*)d_in[iwv[p]] + wofs;
            const float* wo = (const float*)d_in[iwo[p]] + wofs;
            const float* bq = (const float*)d_in[ibq[p]] + bofs;
            const float* bk = (const float*)d_in[ibk[p]] + bofs;
            const float* bv = (const float*)d_in[ibv[p]] + bofs;
            const float* bo = (const float*)d_in[ibo[p]] + bofs;
            const float* gg = (const float*)d_in[ig[p]] + bofs;
            const float* bt = (const float*)d_in[ib[p]] + bofs;

            const float* kv_src = (p == 0) ? x : enc_out;
            const int* tok = (p == 0) ? dec : enc;
            int causal = (p == 0) ? 1 : 0;
            float* S = ((p == 0) ? sa_base : ca_base) + (size_t)l * AW;

            // fused Q/K/V projections
            QKVP qp;
            qp.A[0] = x;  qp.A[1] = kv_src; qp.A[2] = kv_src;
            qp.W[0] = wq; qp.W[1] = wk;     qp.W[2] = wv;
            qp.bias[0] = bq; qp.bias[1] = bk; qp.bias[2] = bv;
            qp.C[0] = q;  qp.C[1] = k;      qp.C[2] = vt;
            gemm_qkv<<<dim3(12, 32), 256, SMEM128>>>(qp);

            // fused scores + mask + softmax -> writes normalized weights to S
            SSP sp{q, k, tok, S, causal};
            scores_softmax<<<dim3(16, BB * NH), 256, SS_SMEM_BYTES>>>(sp);

            GP gp;
            // ctx[b,q,h*64+d] = sum_k S[b,h,q,k] * vt[h*64+d][b*512+k]
            gp = GP{S, LDQ, NH * LL, LL, vt, M, LDQ, 64LL * M, ctxp, DIM, LL, 64,
                    nullptr, nullptr, 512, 0, 0};
            gemm_std<0, 64><<<dim3(1, 4, BB * NH), 256, SMEM64>>>(gp);
            // out proj
            gp = GP{ctxp, DIM, 0, 0, wo, DIM, 0, 0, proj, DIM, 0, 0, bo, nullptr, DIM, 0, 0};
            gemm_std<0, 64><<<dim3(8, 32, 1), 256, SMEM64>>>(gp);
            add_ln<<<M, 256>>>(proj, x, gg, bt, x);
        }

        // FFN
        GP gp;
        gp = GP{x, DIM, 0, 0, ffn_w1 + (size_t)l * FFD * DIM, DIM, 0, 0,
                ffh, FFD, 0, 0, ffn_b1 + (size_t)l * FFD, nullptr, DIM, 1, 0};
        gemm_std<0, 128><<<dim3(16, 32, 1), 256, SMEM128>>>(gp);
        gp = GP{ffh, FFD, 0, 0, ffn_w2 + (size_t)l * DIM * FFD, FFD, 0, 0,
                proj, DIM, 0, 0, ffn_b2 + bofs, nullptr, FFD, 0, 0};
        gemm_std<0, 64><<<dim3(8, 32, 1), 256, SMEM64>>>(gp);
        float* lnout = (l == NLAY - 1) ? out : x;
        add_ln<<<M, 256>>>(proj, x, ffn_g + bofs, ffn_bb + bofs, lnout);
    }
}